// round 7
// baseline (speedup 1.0000x reference)
#include <cuda_runtime.h>
#include <cstdint>

typedef unsigned long long u64;

#define TILE_B 32
#define THREADS 512
#define APAD 36
#define LOG_SQRT_2PI 0.9189385332046727f

__device__ __forceinline__ u64 bcast2(float x) {
    u64 r;
    asm("mov.b64 %0, {%1,%2};" : "=l"(r) : "f"(x), "f"(x));
    return r;
}
__device__ __forceinline__ void ffma2(u64& d, u64 a, u64 b) {
    asm("fma.rn.f32x2 %0, %1, %2, %0;" : "+l"(d) : "l"(a), "l"(b));
}
__device__ __forceinline__ float2 unpack2(u64 v) {
    float2 f;
    asm("mov.b64 {%0,%1}, %2;" : "=f"(f.x), "=f"(f.y) : "l"(v));
    return f;
}
__device__ __forceinline__ float lrelu(float v) { return v > 0.f ? v : 0.01f * v; }

template<int CPT> struct WVec;
template<> struct WVec<4> { typedef float4 T; };
template<> struct WVec<2> { typedef float2 T; };
template<> struct WVec<1> { typedef float  T; };

__device__ __forceinline__ float getc(const float4& v, int i) {
    return i == 0 ? v.x : i == 1 ? v.y : i == 2 ? v.z : v.w;
}
__device__ __forceinline__ float getc(const float2& v, int i) { return i == 0 ? v.x : v.y; }
__device__ __forceinline__ float getc(const float&  v, int)   { return v; }

// Transposed row-paired GEMM: sAT[k][b] (stride APAD) -> sCT[n][b] (stride APAD).
// Every layer uses COLT=128 (col-groups), RG=4 row-groups, RPT=8 rows/thread.
// Thread computes CPT cols x 8 rows as 4 f32x2 row-pair accumulators per col.
// W prefetched PF k-rows ahead (>= L2 latency).
template <int K, int N, int CPT, int PF, bool RELU>
__device__ __forceinline__ void gemm_T2(
    const float* __restrict__ W, const float* __restrict__ bias,
    const float* __restrict__ sAT, float* __restrict__ sCT)
{
    constexpr int COLT = N / CPT;                     // 128 for all layers
    static_assert(COLT * 4 == THREADS, "mapping");
    typedef typename WVec<CPT>::T WT;

    const int t    = threadIdx.x;
    const int col0 = (t % COLT) * CPT;
    const int row0 = (t / COLT) * 8;                  // RPT = 8

    u64 acc[CPT][4];
#pragma unroll
    for (int c = 0; c < CPT; c++)
#pragma unroll
        for (int j = 0; j < 4; j++) acc[c][j] = 0ull;

    const float* Wc = W + col0;
    WT wbuf[PF];
#pragma unroll
    for (int i = 0; i < PF; i++)
        wbuf[i] = *reinterpret_cast<const WT*>(Wc + (size_t)i * N);

#pragma unroll 1
    for (int kb = 0; kb < K; kb += PF) {
#pragma unroll
        for (int u = 0; u < PF; u++) {
            WT wv = wbuf[u];
            if (kb + PF + u < K)
                wbuf[u] = *reinterpret_cast<const WT*>(Wc + (size_t)(kb + PF + u) * N);
            const ulonglong2* ap = reinterpret_cast<const ulonglong2*>(
                sAT + (kb + u) * APAD + row0);
            const ulonglong2 a01 = ap[0];
            const ulonglong2 a23 = ap[1];
#pragma unroll
            for (int c = 0; c < CPT; c++) {
                const u64 b = bcast2(getc(wv, c));
                ffma2(acc[c][0], a01.x, b);
                ffma2(acc[c][1], a01.y, b);
                ffma2(acc[c][2], a23.x, b);
                ffma2(acc[c][3], a23.y, b);
            }
        }
    }

#pragma unroll
    for (int c = 0; c < CPT; c++) {
        const float bc = bias[col0 + c];
        float* dst = sCT + (size_t)(col0 + c) * APAD + row0;
#pragma unroll
        for (int jj = 0; jj < 2; jj++) {
            float2 v0 = unpack2(acc[c][2 * jj]);
            float2 v1 = unpack2(acc[c][2 * jj + 1]);
            float c0 = v0.x + bc, c1 = v0.y + bc, c2 = v1.x + bc, c3 = v1.y + bc;
            if (RELU) { c0 = lrelu(c0); c1 = lrelu(c1); c2 = lrelu(c2); c3 = lrelu(c3); }
            *reinterpret_cast<float4*>(dst + 4 * jj) = make_float4(c0, c1, c2, c3);
        }
    }
}

// Shared memory layout (floats)
#define OFF_INT    0                    // 256*36 = 9216  (obs_stat^T)
#define OFF_GOALT  9216                 // 128*36 = 4608  (obs_goal^T)
#define OFF_AT     13824                // 512*36 = 18432
#define OFF_BT     32256                // 256*36 = 9216
#define OFF_CT     41472                // 256*36 = 9216  (sg^T / h^T)
#define OFF_WGDUP  50688                // 8*520 = 4160   (Wgate dup'd {w,w})
#define OFF_GATE   54848                // 256
#define OFF_SUM1   55104                // 640
#define OFF_SUM2   55744                // 640
#define OFF_ACT    56384                // 640
#define SMEM_FLOATS 57024
#define SMEM_BYTES (SMEM_FLOATS * 4)    // 228096 B
// p-loop reuse of [INT|GOALT|AT] region (free after W2):
#define OFF_WP2DUP 0                    // 40*520 = 20800 (Wp2[p] dup'd {w,w})
#define OFF_PS     20800                // 32*40 = 1280
#define OFF_BP2    22080                // 40

__global__ __launch_bounds__(THREADS, 1) void actor_kernel(
    const float* __restrict__ obs, const float* __restrict__ actions,
    const float* __restrict__ W1, const float* __restrict__ b1,
    const float* __restrict__ W2, const float* __restrict__ b2,
    const float* __restrict__ Wp1, const float* __restrict__ bp1,
    const float* __restrict__ Wp2, const float* __restrict__ bp2,
    const float* __restrict__ Ws1, const float* __restrict__ bs1,
    const float* __restrict__ Ws2, const float* __restrict__ bs2,
    const float* __restrict__ Ws3, const float* __restrict__ bs3,
    const float* __restrict__ Wg1, const float* __restrict__ bg1,
    const float* __restrict__ Wg2, const float* __restrict__ bg2,
    const float* __restrict__ Wg3, const float* __restrict__ bg3,
    const float* __restrict__ Wgate, const float* __restrict__ bgate,
    float* __restrict__ out)
{
    extern __shared__ float sm[];
    float* sInT  = sm + OFF_INT;
    float* sGoalT= sm + OFF_GOALT;
    float* sAT   = sm + OFF_AT;
    float* sBT   = sm + OFF_BT;
    float* sCT   = sm + OFF_CT;
    float* sWgD  = sm + OFF_WGDUP;
    float* sGate = sm + OFF_GATE;
    float* sSum1 = sm + OFF_SUM1;
    float* sSum2 = sm + OFF_SUM2;
    float* sAct  = sm + OFF_ACT;
    float* sWp2D = sm + OFF_WP2DUP;
    float* sPS   = sm + OFF_PS;
    float* sBp2  = sm + OFF_BP2;

    const int t = threadIdx.x;
    const int rowBase = blockIdx.x * TILE_B;

    // ---- load inputs (transposed), stage dup'd Wgate, init sums ----
    {
        for (int i = t; i < 32 * 96; i += THREADS) {
            int b = i & 31, c4 = i >> 5;
            float4 v = *reinterpret_cast<const float4*>(
                obs + (size_t)(rowBase + b) * 384 + c4 * 4);
            int k = c4 * 4;
            if (k < 256) {
                sInT[(k + 0) * APAD + b] = v.x;
                sInT[(k + 1) * APAD + b] = v.y;
                sInT[(k + 2) * APAD + b] = v.z;
                sInT[(k + 3) * APAD + b] = v.w;
            } else {
                int kg = k - 256;
                sGoalT[(kg + 0) * APAD + b] = v.x;
                sGoalT[(kg + 1) * APAD + b] = v.y;
                sGoalT[(kg + 2) * APAD + b] = v.z;
                sGoalT[(kg + 3) * APAD + b] = v.w;
            }
        }
        for (int i = t; i < 640; i += THREADS) sAct[i] = actions[(size_t)rowBase * 20 + i];
        for (int i = t; i < 2048; i += THREADS) {
            int k = i >> 3, p = i & 7;
            *reinterpret_cast<u64*>(sWgD + p * 520 + 2 * k) = bcast2(Wgate[i]);
        }
        for (int i = t; i < 640; i += THREADS) { sSum1[i] = 0.f; sSum2[i] = 0.f; }
    }
    __syncthreads();

    // ---- gate path (lrelu folded into Ws3/Wg3 epilogue) ----
    gemm_T2<256, 512, 4,  8, true>(Ws1, bs1, sInT,   sAT);  __syncthreads();
    gemm_T2<512, 256, 2, 16, true>(Ws2, bs2, sAT,    sBT);  __syncthreads();
    gemm_T2<256, 128, 1, 16, true>(Ws3, bs3, sBT,    sCT);
    gemm_T2<128, 512, 4,  8, true>(Wg1, bg1, sGoalT, sAT);  __syncthreads();
    gemm_T2<512, 256, 2, 16, true>(Wg2, bg2, sAT,    sBT);  __syncthreads();
    gemm_T2<256, 128, 1, 16, true>(Wg3, bg3, sBT,    sCT + 128 * APAD);
    __syncthreads();

    // ---- gate: w_gate[b][p] = exp(sg[b].Wgate[:,p] + bgate[p]) ----
    if (t < 128) {
        const int bp = t & 15, p = t >> 4;
        const float* wg = sWgD + p * 520;
        u64 acc0 = 0ull, acc1 = 0ull;
        const float* aB = sCT + 2 * bp;
#pragma unroll 4
        for (int k = 0; k < 256; k += 2) {
            ulonglong2 wp = *reinterpret_cast<const ulonglong2*>(wg + 2 * k);
            u64 a0 = *reinterpret_cast<const u64*>(aB + k * APAD);
            u64 a1 = *reinterpret_cast<const u64*>(aB + (k + 1) * APAD);
            ffma2(acc0, a0, wp.x);
            ffma2(acc1, a1, wp.y);
        }
        float2 v0 = unpack2(acc0), v1 = unpack2(acc1);
        float bg = bgate[p];
        sGate[(2 * bp) * 8 + p]     = expf(v0.x + v1.x + bg);
        sGate[(2 * bp + 1) * 8 + p] = expf(v0.y + v1.y + bg);
    }

    // ---- primitive trunk (disjoint smem regions vs gate stage) ----
    gemm_T2<256, 512, 4,  8, true>(W1, b1, sInT, sAT); __syncthreads();
    gemm_T2<512, 256, 2, 16, true>(W2, b2, sAT,  sBT); __syncthreads();
    // [INT|GOALT|AT] now free -> Wp2 dup staging + ps

    for (int p = 0; p < 8; p++) {
        const float* wp2 = Wp2 + p * (256 * 40);
        for (int i = t; i < 256 * 40; i += THREADS) {
            int k = i / 40, o = i % 40;
            *reinterpret_cast<u64*>(sWp2D + o * 520 + 2 * k) = bcast2(wp2[i]);
        }
        if (t < 40) sBp2[t] = bp2[p * 40 + t];
        gemm_T2<256, 256, 2, 16, true>(Wp1 + p * (256 * 256), bp1 + p * 256, sBT, sCT);
        __syncthreads();

        if (t < 128) {
            const int bp = t & 15, og = t >> 4;
            u64 acc5[5];
#pragma unroll
            for (int q = 0; q < 5; q++) acc5[q] = 0ull;
            const float* aB = sCT + 2 * bp;
#pragma unroll 2
            for (int k = 0; k < 256; k += 2) {
                u64 a0 = *reinterpret_cast<const u64*>(aB + k * APAD);
                u64 a1 = *reinterpret_cast<const u64*>(aB + (k + 1) * APAD);
#pragma unroll
                for (int q = 0; q < 5; q++) {
                    ulonglong2 wp = *reinterpret_cast<const ulonglong2*>(
                        sWp2D + (og * 5 + q) * 520 + 2 * k);
                    ffma2(acc5[q], a0, wp.x);
                    ffma2(acc5[q], a1, wp.y);
                }
            }
#pragma unroll
            for (int q = 0; q < 5; q++) {
                int o = og * 5 + q;
                float2 v = unpack2(acc5[q]);
                float bb = sBp2[o];
                sPS[(2 * bp) * 40 + o]     = v.x + bb;
                sPS[(2 * bp + 1) * 40 + o] = v.y + bb;
            }
        }
        __syncthreads();

        for (int i = t; i < 640; i += THREADS) {
            int b = i / 20, a = i % 20;
            float mu  = sPS[b * 40 + a];
            float sig = expf(sPS[b * 40 + 20 + a]);
            float inv = sGate[b * 8 + p] / sig;
            sSum1[i] += mu * inv;
            sSum2[i] += inv;
        }
        __syncthreads();
    }

    // ---- final log_prob / entropy ----
    if (t < 32) {
        const int b = t;
        float lp = 0.f, ent = 0.f;
#pragma unroll
        for (int a = 0; a < 20; a++) {
            float s1v = sSum1[b * 20 + a];
            float s2v = sSum2[b * 20 + a];
            float mu = s1v / s2v;
            float z = (sAct[b * 20 + a] - mu) * s2v;
            float ls = -logf(s2v);
            lp  += -0.5f * z * z - ls - LOG_SQRT_2PI;
            ent += 0.5f + LOG_SQRT_2PI + ls;
        }
        size_t row = (size_t)rowBase + b;
        out[row * 2 + 0] = lp;
        out[row * 2 + 1] = ent;
    }
}

extern "C" void kernel_launch(void* const* d_in, const int* in_sizes, int n_in,
                              void* d_out, int out_size)
{
    const float* obs    = (const float*)d_in[0];
    const float* actions= (const float*)d_in[1];
    const float* W1     = (const float*)d_in[2];
    const float* b1     = (const float*)d_in[3];
    const float* W2     = (const float*)d_in[4];
    const float* b2     = (const float*)d_in[5];
    const float* Wp1    = (const float*)d_in[6];
    const float* bp1    = (const float*)d_in[7];
    const float* Wp2    = (const float*)d_in[8];
    const float* bp2    = (const float*)d_in[9];
    const float* Ws1    = (const float*)d_in[10];
    const float* bs1    = (const float*)d_in[11];
    const float* Ws2    = (const float*)d_in[12];
    const float* bs2    = (const float*)d_in[13];
    const float* Ws3    = (const float*)d_in[14];
    const float* bs3    = (const float*)d_in[15];
    const float* Wg1    = (const float*)d_in[16];
    const float* bg1    = (const float*)d_in[17];
    const float* Wg2    = (const float*)d_in[18];
    const float* bg2    = (const float*)d_in[19];
    const float* Wg3    = (const float*)d_in[20];
    const float* bg3    = (const float*)d_in[21];
    const float* Wgate  = (const float*)d_in[22];
    const float* bgate  = (const float*)d_in[23];
    float* out = (float*)d_out;

    cudaFuncSetAttribute(actor_kernel,
                         cudaFuncAttributeMaxDynamicSharedMemorySize, SMEM_BYTES);

    const int grid = 65536 / TILE_B;  // 2048 CTAs
    actor_kernel<<<grid, THREADS, SMEM_BYTES>>>(
        obs, actions, W1, b1, W2, b2, Wp1, bp1, Wp2, bp2,
        Ws1, bs1, Ws2, bs2, Ws3, bs3, Wg1, bg1, Wg2, bg2,
        Wg3, bg3, Wgate, bgate, out);
}

// round 8
// speedup vs baseline: 1.0009x; 1.0009x over previous
#include <cuda_runtime.h>
#include <cstdint>

typedef unsigned long long u64;

#define TILE_B 32
#define THREADS 512
#define APAD 36
#define LOG_SQRT_2PI 0.9189385332046727f

__device__ __forceinline__ u64 bcast2(float x) {
    u64 r;
    asm("mov.b64 %0, {%1,%2};" : "=l"(r) : "f"(x), "f"(x));
    return r;
}
__device__ __forceinline__ void ffma2(u64& d, u64 a, u64 b) {
    asm("fma.rn.f32x2 %0, %1, %2, %0;" : "+l"(d) : "l"(a), "l"(b));
}
__device__ __forceinline__ float2 unpack2(u64 v) {
    float2 f;
    asm("mov.b64 {%0,%1}, %2;" : "=f"(f.x), "=f"(f.y) : "l"(v));
    return f;
}
__device__ __forceinline__ float lrelu(float v) { return v > 0.f ? v : 0.01f * v; }

template<int CPT> struct WVec;
template<> struct WVec<4> { typedef float4 T; };
template<> struct WVec<2> { typedef float2 T; };
template<> struct WVec<1> { typedef float  T; };

__device__ __forceinline__ float getc(const float4& v, int i) {
    return i == 0 ? v.x : i == 1 ? v.y : i == 2 ? v.z : v.w;
}
__device__ __forceinline__ float getc(const float2& v, int i) { return i == 0 ? v.x : v.y; }
__device__ __forceinline__ float getc(const float&  v, int)   { return v; }

// Transposed row-paired GEMM: sAT[k][b] (stride APAD) -> sCT[n][b] (stride APAD).
// Every layer uses COLT=128 (col-groups), RG=4 row-groups, RPT=8 rows/thread.
// Thread computes CPT cols x 8 rows as 4 f32x2 row-pair accumulators per col.
// W prefetched PF k-rows ahead (>= L2 latency).
template <int K, int N, int CPT, int PF, bool RELU>
__device__ __forceinline__ void gemm_T2(
    const float* __restrict__ W, const float* __restrict__ bias,
    const float* __restrict__ sAT, float* __restrict__ sCT)
{
    constexpr int COLT = N / CPT;                     // 128 for all layers
    static_assert(COLT * 4 == THREADS, "mapping");
    typedef typename WVec<CPT>::T WT;

    const int t    = threadIdx.x;
    const int col0 = (t % COLT) * CPT;
    const int row0 = (t / COLT) * 8;                  // RPT = 8

    u64 acc[CPT][4];
#pragma unroll
    for (int c = 0; c < CPT; c++)
#pragma unroll
        for (int j = 0; j < 4; j++) acc[c][j] = 0ull;

    const float* Wc = W + col0;
    WT wbuf[PF];
#pragma unroll
    for (int i = 0; i < PF; i++)
        wbuf[i] = *reinterpret_cast<const WT*>(Wc + (size_t)i * N);

#pragma unroll 1
    for (int kb = 0; kb < K; kb += PF) {
#pragma unroll
        for (int u = 0; u < PF; u++) {
            WT wv = wbuf[u];
            if (kb + PF + u < K)
                wbuf[u] = *reinterpret_cast<const WT*>(Wc + (size_t)(kb + PF + u) * N);
            const ulonglong2* ap = reinterpret_cast<const ulonglong2*>(
                sAT + (kb + u) * APAD + row0);
            const ulonglong2 a01 = ap[0];
            const ulonglong2 a23 = ap[1];
#pragma unroll
            for (int c = 0; c < CPT; c++) {
                const u64 b = bcast2(getc(wv, c));
                ffma2(acc[c][0], a01.x, b);
                ffma2(acc[c][1], a01.y, b);
                ffma2(acc[c][2], a23.x, b);
                ffma2(acc[c][3], a23.y, b);
            }
        }
    }

#pragma unroll
    for (int c = 0; c < CPT; c++) {
        const float bc = bias[col0 + c];
        float* dst = sCT + (size_t)(col0 + c) * APAD + row0;
#pragma unroll
        for (int jj = 0; jj < 2; jj++) {
            float2 v0 = unpack2(acc[c][2 * jj]);
            float2 v1 = unpack2(acc[c][2 * jj + 1]);
            float c0 = v0.x + bc, c1 = v0.y + bc, c2 = v1.x + bc, c3 = v1.y + bc;
            if (RELU) { c0 = lrelu(c0); c1 = lrelu(c1); c2 = lrelu(c2); c3 = lrelu(c3); }
            *reinterpret_cast<float4*>(dst + 4 * jj) = make_float4(c0, c1, c2, c3);
        }
    }
}

// Shared memory layout (floats)
#define OFF_INT    0                    // 256*36 = 9216  (obs_stat^T)
#define OFF_GOALT  9216                 // 128*36 = 4608  (obs_goal^T)
#define OFF_AT     13824                // 512*36 = 18432
#define OFF_BT     32256                // 256*36 = 9216
#define OFF_CT     41472                // 256*36 = 9216  (sg^T / h^T)
#define OFF_WGDUP  50688                // 8*520 = 4160   (Wgate dup'd {w,w})
#define OFF_GATE   54848                // 256
#define OFF_SUM1   55104                // 640
#define OFF_SUM2   55744                // 640
#define OFF_ACT    56384                // 640
#define SMEM_FLOATS 57024
#define SMEM_BYTES (SMEM_FLOATS * 4)    // 228096 B
// p-loop reuse of [INT|GOALT|AT] region (free after W2):
#define OFF_WP2DUP 0                    // 40*520 = 20800 (Wp2[p] dup'd {w,w})
#define OFF_PS     20800                // 32*40 = 1280
#define OFF_BP2    22080                // 40

__global__ __launch_bounds__(THREADS, 1) void actor_kernel(
    const float* __restrict__ obs, const float* __restrict__ actions,
    const float* __restrict__ W1, const float* __restrict__ b1,
    const float* __restrict__ W2, const float* __restrict__ b2,
    const float* __restrict__ Wp1, const float* __restrict__ bp1,
    const float* __restrict__ Wp2, const float* __restrict__ bp2,
    const float* __restrict__ Ws1, const float* __restrict__ bs1,
    const float* __restrict__ Ws2, const float* __restrict__ bs2,
    const float* __restrict__ Ws3, const float* __restrict__ bs3,
    const float* __restrict__ Wg1, const float* __restrict__ bg1,
    const float* __restrict__ Wg2, const float* __restrict__ bg2,
    const float* __restrict__ Wg3, const float* __restrict__ bg3,
    const float* __restrict__ Wgate, const float* __restrict__ bgate,
    float* __restrict__ out)
{
    extern __shared__ float sm[];
    float* sInT  = sm + OFF_INT;
    float* sGoalT= sm + OFF_GOALT;
    float* sAT   = sm + OFF_AT;
    float* sBT   = sm + OFF_BT;
    float* sCT   = sm + OFF_CT;
    float* sWgD  = sm + OFF_WGDUP;
    float* sGate = sm + OFF_GATE;
    float* sSum1 = sm + OFF_SUM1;
    float* sSum2 = sm + OFF_SUM2;
    float* sAct  = sm + OFF_ACT;
    float* sWp2D = sm + OFF_WP2DUP;
    float* sPS   = sm + OFF_PS;
    float* sBp2  = sm + OFF_BP2;

    const int t = threadIdx.x;
    const int rowBase = blockIdx.x * TILE_B;

    // ---- load inputs (transposed), stage dup'd Wgate, init sums ----
    {
        for (int i = t; i < 32 * 96; i += THREADS) {
            int b = i & 31, c4 = i >> 5;
            float4 v = *reinterpret_cast<const float4*>(
                obs + (size_t)(rowBase + b) * 384 + c4 * 4);
            int k = c4 * 4;
            if (k < 256) {
                sInT[(k + 0) * APAD + b] = v.x;
                sInT[(k + 1) * APAD + b] = v.y;
                sInT[(k + 2) * APAD + b] = v.z;
                sInT[(k + 3) * APAD + b] = v.w;
            } else {
                int kg = k - 256;
                sGoalT[(kg + 0) * APAD + b] = v.x;
                sGoalT[(kg + 1) * APAD + b] = v.y;
                sGoalT[(kg + 2) * APAD + b] = v.z;
                sGoalT[(kg + 3) * APAD + b] = v.w;
            }
        }
        for (int i = t; i < 640; i += THREADS) sAct[i] = actions[(size_t)rowBase * 20 + i];
        for (int i = t; i < 2048; i += THREADS) {
            int k = i >> 3, p = i & 7;
            *reinterpret_cast<u64*>(sWgD + p * 520 + 2 * k) = bcast2(Wgate[i]);
        }
        for (int i = t; i < 640; i += THREADS) { sSum1[i] = 0.f; sSum2[i] = 0.f; }
    }
    __syncthreads();

    // ---- gate path (lrelu folded into Ws3/Wg3 epilogue) ----
    gemm_T2<256, 512, 4,  8, true>(Ws1, bs1, sInT,   sAT);  __syncthreads();
    gemm_T2<512, 256, 2, 16, true>(Ws2, bs2, sAT,    sBT);  __syncthreads();
    gemm_T2<256, 128, 1, 16, true>(Ws3, bs3, sBT,    sCT);
    gemm_T2<128, 512, 4,  8, true>(Wg1, bg1, sGoalT, sAT);  __syncthreads();
    gemm_T2<512, 256, 2, 16, true>(Wg2, bg2, sAT,    sBT);  __syncthreads();
    gemm_T2<256, 128, 1, 16, true>(Wg3, bg3, sBT,    sCT + 128 * APAD);
    __syncthreads();

    // ---- gate: w_gate[b][p] = exp(sg[b].Wgate[:,p] + bgate[p]) ----
    if (t < 128) {
        const int bp = t & 15, p = t >> 4;
        const float* wg = sWgD + p * 520;
        u64 acc0 = 0ull, acc1 = 0ull;
        const float* aB = sCT + 2 * bp;
#pragma unroll 4
        for (int k = 0; k < 256; k += 2) {
            ulonglong2 wp = *reinterpret_cast<const ulonglong2*>(wg + 2 * k);
            u64 a0 = *reinterpret_cast<const u64*>(aB + k * APAD);
            u64 a1 = *reinterpret_cast<const u64*>(aB + (k + 1) * APAD);
            ffma2(acc0, a0, wp.x);
            ffma2(acc1, a1, wp.y);
        }
        float2 v0 = unpack2(acc0), v1 = unpack2(acc1);
        float bg = bgate[p];
        sGate[(2 * bp) * 8 + p]     = expf(v0.x + v1.x + bg);
        sGate[(2 * bp + 1) * 8 + p] = expf(v0.y + v1.y + bg);
    }

    // ---- primitive trunk (disjoint smem regions vs gate stage) ----
    gemm_T2<256, 512, 4,  8, true>(W1, b1, sInT, sAT); __syncthreads();
    gemm_T2<512, 256, 2, 16, true>(W2, b2, sAT,  sBT); __syncthreads();
    // [INT|GOALT|AT] now free -> Wp2 dup staging + ps

    for (int p = 0; p < 8; p++) {
        const float* wp2 = Wp2 + p * (256 * 40);
        for (int i = t; i < 256 * 40; i += THREADS) {
            int k = i / 40, o = i % 40;
            *reinterpret_cast<u64*>(sWp2D + o * 520 + 2 * k) = bcast2(wp2[i]);
        }
        if (t < 40) sBp2[t] = bp2[p * 40 + t];
        gemm_T2<256, 256, 2, 16, true>(Wp1 + p * (256 * 256), bp1 + p * 256, sBT, sCT);
        __syncthreads();

        if (t < 128) {
            const int bp = t & 15, og = t >> 4;
            u64 acc5[5];
#pragma unroll
            for (int q = 0; q < 5; q++) acc5[q] = 0ull;
            const float* aB = sCT + 2 * bp;
#pragma unroll 2
            for (int k = 0; k < 256; k += 2) {
                u64 a0 = *reinterpret_cast<const u64*>(aB + k * APAD);
                u64 a1 = *reinterpret_cast<const u64*>(aB + (k + 1) * APAD);
#pragma unroll
                for (int q = 0; q < 5; q++) {
                    ulonglong2 wp = *reinterpret_cast<const ulonglong2*>(
                        sWp2D + (og * 5 + q) * 520 + 2 * k);
                    ffma2(acc5[q], a0, wp.x);
                    ffma2(acc5[q], a1, wp.y);
                }
            }
#pragma unroll
            for (int q = 0; q < 5; q++) {
                int o = og * 5 + q;
                float2 v = unpack2(acc5[q]);
                float bb = sBp2[o];
                sPS[(2 * bp) * 40 + o]     = v.x + bb;
                sPS[(2 * bp + 1) * 40 + o] = v.y + bb;
            }
        }
        __syncthreads();

        for (int i = t; i < 640; i += THREADS) {
            int b = i / 20, a = i % 20;
            float mu  = sPS[b * 40 + a];
            float sig = expf(sPS[b * 40 + 20 + a]);
            float inv = sGate[b * 8 + p] / sig;
            sSum1[i] += mu * inv;
            sSum2[i] += inv;
        }
        __syncthreads();
    }

    // ---- final log_prob / entropy ----
    if (t < 32) {
        const int b = t;
        float lp = 0.f, ent = 0.f;
#pragma unroll
        for (int a = 0; a < 20; a++) {
            float s1v = sSum1[b * 20 + a];
            float s2v = sSum2[b * 20 + a];
            float mu = s1v / s2v;
            float z = (sAct[b * 20 + a] - mu) * s2v;
            float ls = -logf(s2v);
            lp  += -0.5f * z * z - ls - LOG_SQRT_2PI;
            ent += 0.5f + LOG_SQRT_2PI + ls;
        }
        size_t row = (size_t)rowBase + b;
        out[row * 2 + 0] = lp;
        out[row * 2 + 1] = ent;
    }
}

extern "C" void kernel_launch(void* const* d_in, const int* in_sizes, int n_in,
                              void* d_out, int out_size)
{
    const float* obs    = (const float*)d_in[0];
    const float* actions= (const float*)d_in[1];
    const float* W1     = (const float*)d_in[2];
    const float* b1     = (const float*)d_in[3];
    const float* W2     = (const float*)d_in[4];
    const float* b2     = (const float*)d_in[5];
    const float* Wp1    = (const float*)d_in[6];
    const float* bp1    = (const float*)d_in[7];
    const float* Wp2    = (const float*)d_in[8];
    const float* bp2    = (const float*)d_in[9];
    const float* Ws1    = (const float*)d_in[10];
    const float* bs1    = (const float*)d_in[11];
    const float* Ws2    = (const float*)d_in[12];
    const float* bs2    = (const float*)d_in[13];
    const float* Ws3    = (const float*)d_in[14];
    const float* bs3    = (const float*)d_in[15];
    const float* Wg1    = (const float*)d_in[16];
    const float* bg1    = (const float*)d_in[17];
    const float* Wg2    = (const float*)d_in[18];
    const float* bg2    = (const float*)d_in[19];
    const float* Wg3    = (const float*)d_in[20];
    const float* bg3    = (const float*)d_in[21];
    const float* Wgate  = (const float*)d_in[22];
    const float* bgate  = (const float*)d_in[23];
    float* out = (float*)d_out;

    cudaFuncSetAttribute(actor_kernel,
                         cudaFuncAttributeMaxDynamicSharedMemorySize, SMEM_BYTES);

    const int grid = 65536 / TILE_B;  // 2048 CTAs
    actor_kernel<<<grid, THREADS, SMEM_BYTES>>>(
        obs, actions, W1, b1, W2, b2, Wp1, bp1, Wp2, bp2,
        Ws1, bs1, Ws2, bs2, Ws3, bs3, Wg1, bg1, Wg2, bg2,
        Wg3, bg3, Wgate, bgate, out);
}

// round 9
// speedup vs baseline: 2.6108x; 2.6083x over previous
#include <cuda_runtime.h>
#include <cuda_bf16.h>
#include <cstdint>

typedef __nv_bfloat16 bf16;
#define THREADS 512
#define LOG_SQRT_2PI 0.9189385332046727f

// ---------- packed weights: per (16k x 8n) block, 256 bf16 (B-frag order, hi+lo) ----------
__device__ bf16 g_wpack[2785280];   // 10880 blocks * 256

struct LDesc { int K, N, base, sid, soff; };
__constant__ LDesc c_layers[24] = {
    {256,512,0,0,0},{512,256,1024,1,0},
    {256,256,2048,2,0},{256,256,2560,2,65536},{256,256,3072,2,131072},{256,256,3584,2,196608},
    {256,256,4096,2,262144},{256,256,4608,2,327680},{256,256,5120,2,393216},{256,256,5632,2,458752},
    {256,40,6144,3,0},{256,40,6224,3,10240},{256,40,6304,3,20480},{256,40,6384,3,30720},
    {256,40,6464,3,40960},{256,40,6544,3,51200},{256,40,6624,3,61440},{256,40,6704,3,71680},
    {256,512,6784,4,0},{512,256,7808,5,0},{256,128,8832,6,0},
    {128,512,9088,7,0},{512,256,9600,8,0},{256,128,10624,9,0}
};
__constant__ long c_prefix[25] = {
    0,131072,262144,327680,393216,458752,524288,589824,655360,720896,786432,
    796672,806912,817152,827392,837632,847872,858112,868352,
    999424,1130496,1163264,1228800,1359872,1392640
};

struct PrepArgs { const float* s[10]; };

__global__ void prep_kernel(PrepArgs a) {
    long i = (long)blockIdx.x * 256 + threadIdx.x;
    if (i >= 1392640L) return;
    int L = 0;
    while (c_prefix[L + 1] <= i) L++;
    LDesc d = c_layers[L];
    int e = (int)(i - c_prefix[L]);
    int k = e / d.N, n = e % d.N;
    float w = a.s[d.sid][(size_t)d.soff + e];
    bf16 hi = __float2bfloat16(w);
    bf16 lo = __float2bfloat16(w - __bfloat162float(hi));
    int blk = d.base + (n >> 3) * (d.K >> 4) + (k >> 4);
    int r = k & 15;
    int lane = (n & 7) * 4 + ((r & 7) >> 1);
    int sub = (r & 1) + ((r >= 8) ? 2 : 0);
    bf16* dst = g_wpack + (long)blk * 256 + lane * 8;
    dst[sub] = hi;
    dst[sub + 4] = lo;
}

// ---------- main kernel helpers ----------
__device__ __forceinline__ uint32_t s2u(const void* p) {
    return (uint32_t)__cvta_generic_to_shared(p);
}
__device__ __forceinline__ void ldsm4(uint32_t a, uint32_t* r) {
    asm volatile("ldmatrix.sync.aligned.m8n8.x4.shared.b16 {%0,%1,%2,%3}, [%4];"
        : "=r"(r[0]), "=r"(r[1]), "=r"(r[2]), "=r"(r[3]) : "r"(a));
}
__device__ __forceinline__ void hmma(float* d, const uint32_t* a, uint32_t b0, uint32_t b1) {
    asm volatile("mma.sync.aligned.m16n8k16.row.col.f32.bf16.bf16.f32 "
        "{%0,%1,%2,%3}, {%4,%5,%6,%7}, {%8,%9}, {%0,%1,%2,%3};"
        : "+f"(d[0]), "+f"(d[1]), "+f"(d[2]), "+f"(d[3])
        : "r"(a[0]), "r"(a[1]), "r"(a[2]), "r"(a[3]), "r"(b0), "r"(b1));
}
__device__ __forceinline__ float lrelu(float v) { return v > 0.f ? v : 0.01f * v; }
__device__ __forceinline__ void zeroD(float D[4][4]) {
#pragma unroll
    for (int j = 0; j < 4; j++)
#pragma unroll
        for (int i = 0; i < 4; i++) D[j][i] = 0.f;
}

// accumulate: D[j] += A(region) @ B(ntile = wc + 8j), k-tiles 0..KT-1
template <int NTW, int KT>
__device__ __forceinline__ void mma_pass(
    float D[4][4], int blkBase, int ktStride,
    uint32_t aHiA, uint32_t aLoA, int sp, int mt, int wc, int lane)
{
    uint32_t off = (uint32_t)(((mt * 16 + (lane & 15)) * sp + (lane >> 4) * 8) * 2);
    uint32_t ah0 = aHiA + off, al0 = aLoA + off;
    const uint4* bp[NTW];
#pragma unroll
    for (int j = 0; j < NTW; j++)
        bp[j] = reinterpret_cast<const uint4*>(
                    g_wpack + (long)(blkBase + (wc + 8 * j) * ktStride) * 256) + lane;
    uint4 bc[NTW];
#pragma unroll
    for (int j = 0; j < NTW; j++) bc[j] = bp[j][0];
#pragma unroll 1
    for (int kt = 0; kt < KT; kt++) {
        uint32_t ah[4], al[4];
        ldsm4(ah0 + kt * 32, ah);
        ldsm4(al0 + kt * 32, al);
        uint4 bn[NTW];
        if (kt + 1 < KT) {
#pragma unroll
            for (int j = 0; j < NTW; j++) bn[j] = bp[j][(kt + 1) * 32];
        }
#pragma unroll
        for (int j = 0; j < NTW; j++) {
            hmma(D[j], ah, bc[j].x, bc[j].y);   // Ahi*Bhi
            hmma(D[j], ah, bc[j].z, bc[j].w);   // Ahi*Blo
            hmma(D[j], al, bc[j].x, bc[j].y);   // Alo*Bhi
        }
#pragma unroll
        for (int j = 0; j < NTW; j++) bc[j] = bn[j];
    }
}

// epilogue: +bias (+lrelu) -> hi/lo bf16 region
template <int NTW, bool RELU>
__device__ __forceinline__ void epi_bf(
    float D[4][4], const float* bias, bf16* dHi, bf16* dLo,
    int sp, int mt, int wc, int lane)
{
    int r0 = lane >> 2, c0 = (lane & 3) * 2;
#pragma unroll
    for (int j = 0; j < NTW; j++) {
        int col = (wc + 8 * j) * 8 + c0;
        float b0 = bias[col], b1 = bias[col + 1];
#pragma unroll
        for (int h = 0; h < 2; h++) {
            int row = mt * 16 + r0 + h * 8;
            float v0 = D[j][2 * h] + b0, v1 = D[j][2 * h + 1] + b1;
            if (RELU) { v0 = lrelu(v0); v1 = lrelu(v1); }
            bf16 h0 = __float2bfloat16(v0), h1 = __float2bfloat16(v1);
            bf16 g0 = __float2bfloat16(v0 - __bfloat162float(h0));
            bf16 g1 = __float2bfloat16(v1 - __bfloat162float(h1));
            *(uint32_t*)(dHi + row * sp + col) =
                ((uint32_t)__bfloat16_as_ushort(h1) << 16) | __bfloat16_as_ushort(h0);
            *(uint32_t*)(dLo + row * sp + col) =
                ((uint32_t)__bfloat16_as_ushort(g1) << 16) | __bfloat16_as_ushort(g0);
        }
    }
}

// smem byte offsets
#define O_RINH 0
#define O_RINL 16896
#define O_RGLH 33792
#define O_RGLL 42496
#define O_RAH  51200
#define O_RAL  84480
#define O_RBH  117760
#define O_RBL  134656
#define O_RCH  151552
#define O_RCL  168448
#define O_WG   185344
#define O_GATE 193536
#define O_SUM1 194560
#define O_SUM2 197120
#define O_ACT  199680
#define O_PS   202240
#define SMEM_BYTES 207872

__global__ __launch_bounds__(THREADS, 1) void actor_kernel(
    const float* __restrict__ obs, const float* __restrict__ actions,
    const float* __restrict__ b1, const float* __restrict__ b2,
    const float* __restrict__ bp1, const float* __restrict__ bp2,
    const float* __restrict__ bs1, const float* __restrict__ bs2,
    const float* __restrict__ bs3, const float* __restrict__ bg1,
    const float* __restrict__ bg2, const float* __restrict__ bg3,
    const float* __restrict__ Wgate, const float* __restrict__ bgate,
    float* __restrict__ out)
{
    extern __shared__ char sm[];
    bf16* RINh = (bf16*)(sm + O_RINH); bf16* RINl = (bf16*)(sm + O_RINL);
    bf16* RGLh = (bf16*)(sm + O_RGLH); bf16* RGLl = (bf16*)(sm + O_RGLL);
    bf16* RAh  = (bf16*)(sm + O_RAH);  bf16* RAl  = (bf16*)(sm + O_RAL);
    bf16* RBh  = (bf16*)(sm + O_RBH);  bf16* RBl  = (bf16*)(sm + O_RBL);
    bf16* RCh  = (bf16*)(sm + O_RCH);  bf16* RCl  = (bf16*)(sm + O_RCL);
    float* sWg   = (float*)(sm + O_WG);
    float* sGate = (float*)(sm + O_GATE);
    float* sSum1 = (float*)(sm + O_SUM1);
    float* sSum2 = (float*)(sm + O_SUM2);
    float* sAct  = (float*)(sm + O_ACT);
    float* sPS   = (float*)(sm + O_PS);

    const uint32_t RINhA = s2u(RINh), RINlA = s2u(RINl);
    const uint32_t RGLhA = s2u(RGLh), RGLlA = s2u(RGLl);
    const uint32_t RAhA  = s2u(RAh),  RAlA  = s2u(RAl);
    const uint32_t RBhA  = s2u(RBh),  RBlA  = s2u(RBl);
    const uint32_t RChA  = s2u(RCh),  RClA  = s2u(RCl);

    const int t = threadIdx.x;
    const int lane = t & 31, w = t >> 5;
    const int mt = w & 1, wc = w >> 1;
    const int rowBase = blockIdx.x * 32;

    // ---- inputs -> hi/lo bf16, misc staging ----
    for (int i = t; i < 32 * 96; i += THREADS) {
        int b = i / 96, c4 = i % 96;
        float4 v = *reinterpret_cast<const float4*>(obs + (size_t)(rowBase + b) * 384 + c4 * 4);
        bf16 *ph, *pl;
        int c;
        if (c4 < 64) { c = c4 * 4; ph = RINh + b * 264 + c; pl = RINl + b * 264 + c; }
        else         { c = (c4 - 64) * 4; ph = RGLh + b * 136 + c; pl = RGLl + b * 136 + c; }
        float vv[4] = {v.x, v.y, v.z, v.w};
#pragma unroll
        for (int q = 0; q < 4; q++) {
            bf16 h = __float2bfloat16(vv[q]);
            ph[q] = h;
            pl[q] = __float2bfloat16(vv[q] - __bfloat162float(h));
        }
    }
    for (int i = t; i < 640; i += THREADS) {
        sAct[i] = actions[(size_t)rowBase * 20 + i];
        sSum1[i] = 0.f; sSum2[i] = 0.f;
    }
    for (int i = t; i < 2048; i += THREADS) sWg[i] = Wgate[i];
    __syncthreads();

    float D[4][4];
    // ---- gate path ----
    zeroD(D); mma_pass<4,16>(D, 6784,      16, RINhA, RINlA, 264, mt, wc, lane);
    epi_bf<4,true>(D, bs1,       RAh,       RAl,       520, mt, wc, lane);
    zeroD(D); mma_pass<4,16>(D, 6784+512,  16, RINhA, RINlA, 264, mt, wc, lane);
    epi_bf<4,true>(D, bs1 + 256, RAh + 256, RAl + 256, 520, mt, wc, lane);
    __syncthreads();
    zeroD(D); mma_pass<4,32>(D, 7808, 32, RAhA, RAlA, 520, mt, wc, lane);
    epi_bf<4,true>(D, bs2, RBh, RBl, 264, mt, wc, lane);
    __syncthreads();
    zeroD(D); mma_pass<2,16>(D, 8832, 16, RBhA, RBlA, 264, mt, wc, lane);
    epi_bf<2,true>(D, bs3, RCh, RCl, 264, mt, wc, lane);      // sg[:,0:128]
    zeroD(D); mma_pass<4,8>(D, 9088,      8, RGLhA, RGLlA, 136, mt, wc, lane);
    epi_bf<4,true>(D, bg1,       RAh,       RAl,       520, mt, wc, lane);
    zeroD(D); mma_pass<4,8>(D, 9088+256,  8, RGLhA, RGLlA, 136, mt, wc, lane);
    epi_bf<4,true>(D, bg1 + 256, RAh + 256, RAl + 256, 520, mt, wc, lane);
    __syncthreads();
    zeroD(D); mma_pass<4,32>(D, 9600, 32, RAhA, RAlA, 520, mt, wc, lane);
    epi_bf<4,true>(D, bg2, RBh, RBl, 264, mt, wc, lane);
    __syncthreads();
    zeroD(D); mma_pass<2,16>(D, 10624, 16, RBhA, RBlA, 264, mt, wc, lane);
    epi_bf<2,true>(D, bg3, RCh + 128, RCl + 128, 264, mt, wc, lane);  // sg[:,128:256]
    __syncthreads();

    // ---- gate: w_gate[b][p] = exp(sg[b].Wgate[:,p] + bgate[p]) ----
    if (t < 256) {
        int b = t >> 3, p = t & 7;
        float acc = 0.f;
        for (int k = 0; k < 256; k++) {
            float s = __bfloat162float(RCh[b * 264 + k]) + __bfloat162float(RCl[b * 264 + k]);
            acc += s * sWg[k * 8 + p];
        }
        sGate[t] = expf(acc + bgate[p]);
    }

    // ---- primitive trunk ----
    zeroD(D); mma_pass<4,16>(D, 0,   16, RINhA, RINlA, 264, mt, wc, lane);
    epi_bf<4,true>(D, b1,       RAh,       RAl,       520, mt, wc, lane);
    zeroD(D); mma_pass<4,16>(D, 512, 16, RINhA, RINlA, 264, mt, wc, lane);
    epi_bf<4,true>(D, b1 + 256, RAh + 256, RAl + 256, 520, mt, wc, lane);
    __syncthreads();
    zeroD(D); mma_pass<4,32>(D, 1024, 32, RAhA, RAlA, 520, mt, wc, lane);
    epi_bf<4,true>(D, b2, RBh, RBl, 264, mt, wc, lane);   // s1 stays in RB
    __syncthreads();

    for (int p = 0; p < 8; p++) {
        zeroD(D); mma_pass<4,16>(D, 2048 + p * 512, 16, RBhA, RBlA, 264, mt, wc, lane);
        epi_bf<4,true>(D, bp1 + p * 256, RCh, RCl, 264, mt, wc, lane);   // h
        __syncthreads();
        if (wc < 5) {
            zeroD(D); mma_pass<1,16>(D, 6144 + p * 80, 16, RChA, RClA, 264, mt, wc, lane);
            int r0 = lane >> 2, c0 = (lane & 3) * 2;
            int col = wc * 8 + c0;
            float bb0 = bp2[p * 40 + col], bb1 = bp2[p * 40 + col + 1];
#pragma unroll
            for (int h = 0; h < 2; h++) {
                int row = mt * 16 + r0 + h * 8;
                sPS[row * 44 + col]     = D[0][2 * h]     + bb0;
                sPS[row * 44 + col + 1] = D[0][2 * h + 1] + bb1;
            }
        }
        __syncthreads();
        for (int i = t; i < 640; i += THREADS) {
            int b = i / 20, a = i % 20;
            float mu  = sPS[b * 44 + a];
            float sig = expf(sPS[b * 44 + 20 + a]);
            float inv = sGate[b * 8 + p] / sig;
            sSum1[i] += mu * inv;
            sSum2[i] += inv;
        }
        __syncthreads();
    }

    // ---- final log_prob / entropy ----
    if (t < 32) {
        int b = t;
        float lp = 0.f, ent = 0.f;
#pragma unroll
        for (int a = 0; a < 20; a++) {
            float s1v = sSum1[b * 20 + a];
            float s2v = sSum2[b * 20 + a];
            float mu = s1v / s2v;
            float z = (sAct[b * 20 + a] - mu) * s2v;
            float ls = -logf(s2v);
            lp  += -0.5f * z * z - ls - LOG_SQRT_2PI;
            ent += 0.5f + LOG_SQRT_2PI + ls;
        }
        size_t row = (size_t)rowBase + b;
        out[row * 2 + 0] = lp;
        out[row * 2 + 1] = ent;
    }
}

extern "C" void kernel_launch(void* const* d_in, const int* in_sizes, int n_in,
                              void* d_out, int out_size)
{
    PrepArgs pa;
    pa.s[0] = (const float*)d_in[2];   // W1
    pa.s[1] = (const float*)d_in[4];   // W2
    pa.s[2] = (const float*)d_in[6];   // Wp1
    pa.s[3] = (const float*)d_in[8];   // Wp2
    pa.s[4] = (const float*)d_in[10];  // Ws1
    pa.s[5] = (const float*)d_in[12];  // Ws2
    pa.s[6] = (const float*)d_in[14];  // Ws3
    pa.s[7] = (const float*)d_in[16];  // Wg1
    pa.s[8] = (const float*)d_in[18];  // Wg2
    pa.s[9] = (const float*)d_in[20];  // Wg3
    prep_kernel<<<(1392640 + 255) / 256, 256>>>(pa);

    cudaFuncSetAttribute(actor_kernel,
                         cudaFuncAttributeMaxDynamicSharedMemorySize, SMEM_BYTES);
    actor_kernel<<<2048, THREADS, SMEM_BYTES>>>(
        (const float*)d_in[0], (const float*)d_in[1],
        (const float*)d_in[3], (const float*)d_in[5],
        (const float*)d_in[7], (const float*)d_in[9],
        (const float*)d_in[11], (const float*)d_in[13],
        (const float*)d_in[15], (const float*)d_in[17],
        (const float*)d_in[19], (const float*)d_in[21],
        (const float*)d_in[22], (const float*)d_in[23],
        (float*)d_out);
}